// round 3
// baseline (speedup 1.0000x reference)
#include <cuda_runtime.h>
#include <cstdint>

// ---- JAX threefry mode: 1 = partitionable (jax >= 0.4.36 default), 0 = original
#define JAX_THREEFRY_PARTITIONABLE 1

#define NMAX 50000
#define EMAX 800000
#define DIM  128
#define ODIM 64
#define PAD  40   // sA row stride (floats); 160B keeps float4 alignment

// ---------------- scratch (device globals; no allocations) ----------------
__device__ float g_h[NMAX * DIM];   // layer output
__device__ float g_z[NMAX * DIM];   // aggregated input (x + sum neighbors)
__device__ float g_t[NMAX * DIM];   // MLP intermediate
__device__ int   g_rowptr[NMAX + 1];
__device__ int   g_cursor[NMAX];
__device__ int   g_srcs[EMAX];

// ---------------- threefry2x32 (exact JAX) ----------------
__host__ __device__ __forceinline__ unsigned rotl32(unsigned x, int r) {
    return (x << r) | (x >> (32 - r));
}

__host__ __device__ __forceinline__ void threefry2x32(
    unsigned k0, unsigned k1, unsigned x0, unsigned x1,
    unsigned& o0, unsigned& o1)
{
    unsigned ks0 = k0, ks1 = k1, ks2 = k0 ^ k1 ^ 0x1BD11BDAu;
    x0 += ks0; x1 += ks1;
#define TFR(r) { x0 += x1; x1 = rotl32(x1, r); x1 ^= x0; }
    TFR(13) TFR(15) TFR(26) TFR(6)   x0 += ks1; x1 += ks2 + 1u;
    TFR(17) TFR(29) TFR(16) TFR(24)  x0 += ks2; x1 += ks0 + 2u;
    TFR(13) TFR(15) TFR(26) TFR(6)   x0 += ks0; x1 += ks1 + 3u;
    TFR(17) TFR(29) TFR(16) TFR(24)  x0 += ks1; x1 += ks2 + 4u;
    TFR(13) TFR(15) TFR(26) TFR(6)   x0 += ks2; x1 += ks0 + 5u;
#undef TFR
    o0 = x0; o1 = x1;
}

// dropout multiplier: 1/0.9 if kept, 0 if dropped; bit-exact vs jax.random.bernoulli
__device__ __forceinline__ float dropout_mult(unsigned k0, unsigned k1, unsigned j) {
    unsigned a, b, bits;
#if JAX_THREEFRY_PARTITIONABLE
    threefry2x32(k0, k1, 0u, j, a, b);
    bits = a ^ b;
#else
    const unsigned HALF = (unsigned)(NMAX * DIM / 2);  // 3,200,000
    if (j < HALF) { threefry2x32(k0, k1, j, j + HALF, a, b); bits = a; }
    else          { threefry2x32(k0, k1, j - HALF, j, a, b); bits = b; }
#endif
    float u = __uint_as_float((bits >> 9) | 0x3f800000u) - 1.0f;
    return (u < 0.9f) ? (1.0f / 0.9f) : 0.0f;
}

// ---------------- CSR build (edge_index is INT32: row0=src[e], row1=dst[e]) --
__global__ void k_zero(int n) {
    int i = blockIdx.x * blockDim.x + threadIdx.x;
    if (i < n) g_cursor[i] = 0;
}

__global__ void k_hist(const int* __restrict__ ei, int e, int n) {
    int idx = blockIdx.x * blockDim.x + threadIdx.x;
    if (idx < e) {
        int dst = ei[e + idx];
        if ((unsigned)dst < (unsigned)n)
            atomicAdd(&g_cursor[dst], 1);
    }
}

__global__ void k_scan(int n) {
    __shared__ int wsum[32];
    __shared__ int carry;
    int t = threadIdx.x, lane = t & 31, w = t >> 5;
    if (t == 0) carry = 0;
    __syncthreads();
    for (int base = 0; base < n; base += 1024) {
        int i = base + t;
        int v = (i < n) ? g_cursor[i] : 0;
        int x = v;
#pragma unroll
        for (int off = 1; off < 32; off <<= 1) {
            int y = __shfl_up_sync(0xffffffffu, x, off);
            if (lane >= off) x += y;
        }
        if (lane == 31) wsum[w] = x;
        __syncthreads();
        if (w == 0) {
            int y = wsum[lane];
#pragma unroll
            for (int off = 1; off < 32; off <<= 1) {
                int z2 = __shfl_up_sync(0xffffffffu, y, off);
                if (lane >= off) y += z2;
            }
            wsum[lane] = y;
        }
        __syncthreads();
        int incl = x + (w ? wsum[w - 1] : 0);
        int excl = carry + incl - v;
        if (i < n) { g_rowptr[i] = excl; g_cursor[i] = excl; }
        __syncthreads();
        if (t == 1023) carry += wsum[31];
        __syncthreads();
    }
    if (t == 0) g_rowptr[n] = carry;
}

__global__ void k_scatter(const int* __restrict__ ei, int e, int n) {
    int idx = blockIdx.x * blockDim.x + threadIdx.x;
    if (idx < e) {
        int dst = ei[e + idx];
        int src = ei[idx];
        if ((unsigned)dst < (unsigned)n && (unsigned)src < (unsigned)n) {
            int pos = atomicAdd(&g_cursor[dst], 1);
            if ((unsigned)pos < (unsigned)EMAX)
                g_srcs[pos] = src;
        }
    }
}

// ---------- aggregation: g_z[i] = base[i] + sum_{src in in(i)} base[src] ----
// base = x (layer 0) or g_h (later layers)
__global__ __launch_bounds__(DIM) void k_aggregate(
    const float* __restrict__ xin, int use_x, int n)
{
    int i = blockIdx.x;
    if (i >= n) return;
    const float* base = use_x ? xin : g_h;
    int d = threadIdx.x;
    float acc = base[(size_t)i * DIM + d];
    int p = g_rowptr[i];
    const int pe = g_rowptr[i + 1];
    for (; p + 4 <= pe; p += 4) {
        int s0 = g_srcs[p], s1 = g_srcs[p + 1], s2 = g_srcs[p + 2], s3 = g_srcs[p + 3];
        float v0 = base[(size_t)s0 * DIM + d];
        float v1 = base[(size_t)s1 * DIM + d];
        float v2 = base[(size_t)s2 * DIM + d];
        float v3 = base[(size_t)s3 * DIM + d];
        acc += v0; acc += v1; acc += v2; acc += v3;
    }
    for (; p < pe; ++p) acc += base[(size_t)g_srcs[p] * DIM + d];
    g_z[(size_t)i * DIM + d] = acc;
}

// ---------------- GEMM 128x128: C = epi(A @ W + b) ------------------------
// A: nrows x 128 (asel: 0 = g_z, 1 = g_t); C: (csel: 0 = g_t, 1 = g_h)
// mode 0: relu;  mode 1: relu + exact-JAX dropout
__global__ __launch_bounds__(256, 1) void k_gemm128(
    const float* __restrict__ Wg, const float* __restrict__ bg,
    int asel, int csel, int mode,
    unsigned dk0, unsigned dk1, int nrows)
{
    __shared__ float sA[128 * PAD];   // 20,480 B
    __shared__ float sW[32 * 128];    // 16,384 B

    const float* A = asel ? g_t : g_z;
    float*       C = csel ? g_h : g_t;

    const int tid = threadIdx.x;
    const int tx8 = (tid & 15) * 8;
    const int ty8 = (tid >> 4) * 8;
    const int row0 = blockIdx.x * 128;
    const int avail = (nrows - row0 < 128) ? (nrows - row0) : 128;

    float acc[8][8];
#pragma unroll
    for (int r = 0; r < 8; r++)
#pragma unroll
        for (int c = 0; c < 8; c++) acc[r][c] = 0.0f;

    for (int kc = 0; kc < 128; kc += 32) {
        // stage A chunk: 128 rows x 32 k
#pragma unroll
        for (int i = tid; i < 1024; i += 256) {
            int r = i >> 3;
            int c4 = (i & 7) * 4;
            float4 v = make_float4(0.f, 0.f, 0.f, 0.f);
            if (r < avail)
                v = *(const float4*)(A + (size_t)(row0 + r) * DIM + kc + c4);
            *(float4*)(sA + r * PAD + c4) = v;
        }
        // stage W chunk: 32 k x 128 cols
#pragma unroll
        for (int i = tid; i < 1024; i += 256) {
            int r = i >> 5;
            int c4 = (i & 31) * 4;
            *(float4*)(sW + r * 128 + c4) =
                *(const float4*)(Wg + (size_t)(kc + r) * 128 + c4);
        }
        __syncthreads();

#pragma unroll
        for (int k = 0; k < 32; k += 4) {
            float4 a[8];
#pragma unroll
            for (int r = 0; r < 8; r++)
                a[r] = *(const float4*)(sA + (ty8 + r) * PAD + k);
#pragma unroll
            for (int kk = 0; kk < 4; kk++) {
                const float4 w0 = *(const float4*)(sW + (k + kk) * 128 + tx8);
                const float4 w1 = *(const float4*)(sW + (k + kk) * 128 + tx8 + 4);
#pragma unroll
                for (int r = 0; r < 8; r++) {
                    const float av = (kk == 0) ? a[r].x : (kk == 1) ? a[r].y
                                   : (kk == 2) ? a[r].z : a[r].w;
                    acc[r][0] = fmaf(av, w0.x, acc[r][0]);
                    acc[r][1] = fmaf(av, w0.y, acc[r][1]);
                    acc[r][2] = fmaf(av, w0.z, acc[r][2]);
                    acc[r][3] = fmaf(av, w0.w, acc[r][3]);
                    acc[r][4] = fmaf(av, w1.x, acc[r][4]);
                    acc[r][5] = fmaf(av, w1.y, acc[r][5]);
                    acc[r][6] = fmaf(av, w1.z, acc[r][6]);
                    acc[r][7] = fmaf(av, w1.w, acc[r][7]);
                }
            }
        }
        __syncthreads();
    }

    // epilogue
    float b[8];
#pragma unroll
    for (int c = 0; c < 8; c++) b[c] = bg[tx8 + c];

#pragma unroll
    for (int r = 0; r < 8; r++) {
        int grow = row0 + ty8 + r;
        if (grow >= nrows) break;
        float v[8];
        if (mode == 0) {
#pragma unroll
            for (int c = 0; c < 8; c++)
                v[c] = fmaxf(acc[r][c] + b[c], 0.f);
        } else {
#pragma unroll
            for (int c = 0; c < 8; c++) {
                float t = fmaxf(acc[r][c] + b[c], 0.f);
                unsigned j = (unsigned)grow * (unsigned)DIM + (unsigned)(tx8 + c);
                v[c] = t * dropout_mult(dk0, dk1, j);
            }
        }
        float4* o = (float4*)(C + (size_t)grow * DIM + tx8);
        o[0] = make_float4(v[0], v[1], v[2], v[3]);
        o[1] = make_float4(v[4], v[5], v[6], v[7]);
    }
}

// ---------------- final linear: out = g_h @ Wlin + blin (128 -> 64) --------
__global__ __launch_bounds__(256, 1) void k_linear(
    const float* __restrict__ Wg, const float* __restrict__ bg,
    float* __restrict__ out, int nrows)
{
    __shared__ float sA[128 * PAD];   // 20,480 B
    __shared__ float sW[32 * 64];     //  8,192 B

    const int tid = threadIdx.x;
    const int tx4 = (tid & 15) * 4;   // 64 cols
    const int ty8 = (tid >> 4) * 8;   // 128 rows
    const int row0 = blockIdx.x * 128;
    const int avail = (nrows - row0 < 128) ? (nrows - row0) : 128;

    float acc[8][4];
#pragma unroll
    for (int r = 0; r < 8; r++)
#pragma unroll
        for (int c = 0; c < 4; c++) acc[r][c] = 0.0f;

    for (int kc = 0; kc < 128; kc += 32) {
#pragma unroll
        for (int i = tid; i < 1024; i += 256) {
            int r = i >> 3;
            int c4 = (i & 7) * 4;
            float4 v = make_float4(0.f, 0.f, 0.f, 0.f);
            if (r < avail)
                v = *(const float4*)(g_h + (size_t)(row0 + r) * DIM + kc + c4);
            *(float4*)(sA + r * PAD + c4) = v;
        }
#pragma unroll
        for (int i = tid; i < 512; i += 256) {
            int r = i >> 4;
            int c4 = (i & 15) * 4;
            *(float4*)(sW + r * 64 + c4) =
                *(const float4*)(Wg + (size_t)(kc + r) * ODIM + c4);
        }
        __syncthreads();

#pragma unroll
        for (int k = 0; k < 32; k += 4) {
            float4 a[8];
#pragma unroll
            for (int r = 0; r < 8; r++)
                a[r] = *(const float4*)(sA + (ty8 + r) * PAD + k);
#pragma unroll
            for (int kk = 0; kk < 4; kk++) {
                const float4 w = *(const float4*)(sW + (k + kk) * 64 + tx4);
#pragma unroll
                for (int r = 0; r < 8; r++) {
                    const float av = (kk == 0) ? a[r].x : (kk == 1) ? a[r].y
                                   : (kk == 2) ? a[r].z : a[r].w;
                    acc[r][0] = fmaf(av, w.x, acc[r][0]);
                    acc[r][1] = fmaf(av, w.y, acc[r][1]);
                    acc[r][2] = fmaf(av, w.z, acc[r][2]);
                    acc[r][3] = fmaf(av, w.w, acc[r][3]);
                }
            }
        }
        __syncthreads();
    }

    float b[4];
#pragma unroll
    for (int c = 0; c < 4; c++) b[c] = bg[tx4 + c];
#pragma unroll
    for (int r = 0; r < 8; r++) {
        int grow = row0 + ty8 + r;
        if (grow >= nrows) break;
        *(float4*)(out + (size_t)grow * ODIM + tx4) =
            make_float4(acc[r][0] + b[0], acc[r][1] + b[1],
                        acc[r][2] + b[2], acc[r][3] + b[3]);
    }
}

// ---------------- launch (kernel launches ONLY — no other CUDA API) --------
extern "C" void kernel_launch(void* const* d_in, const int* in_sizes, int n_in,
                              void* d_out, int out_size)
{
    const float* x    = (const float*)d_in[0];
    const int*   ei   = (const int*)d_in[1];      // int32 edge_index (JAX x64 off)
    const float* Ws1  = (const float*)d_in[2];
    const float* bs1  = (const float*)d_in[3];
    const float* Ws2  = (const float*)d_in[4];
    const float* bs2  = (const float*)d_in[5];
    const float* Wlin = (const float*)d_in[6];
    const float* blin = (const float*)d_in[7];
    float*       out  = (float*)d_out;

    const int n = in_sizes[0] / DIM;
    const int e = in_sizes[1] / 2;
    if (n > NMAX || e > EMAX || n <= 0) return;

    // dropout keys: jax.random.split(jax.random.key(42), 3)
    unsigned dk0[3], dk1[3];
#if JAX_THREEFRY_PARTITIONABLE
    for (int l = 0; l < 3; l++)
        threefry2x32(0u, 42u, 0u, (unsigned)l, dk0[l], dk1[l]);
#else
    {
        unsigned a0, b0, a1, b1, a2, b2;
        threefry2x32(0u, 42u, 0u, 3u, a0, b0);
        threefry2x32(0u, 42u, 1u, 4u, a1, b1);
        threefry2x32(0u, 42u, 2u, 5u, a2, b2);
        dk0[0] = a0; dk1[0] = a1;
        dk0[1] = a2; dk1[1] = b0;
        dk0[2] = b1; dk1[2] = b2;
    }
#endif

    // CSR build (shared across all 3 layers)
    k_zero   <<<(n + 255) / 256, 256>>>(n);
    k_hist   <<<(e + 255) / 256, 256>>>(ei, e, n);
    k_scan   <<<1, 1024>>>(n);
    k_scatter<<<(e + 255) / 256, 256>>>(ei, e, n);

    const int gblk = (n + 127) / 128;
    for (int l = 0; l < 3; l++) {
        k_aggregate<<<n, DIM>>>(x, l == 0 ? 1 : 0, n);
        // t = relu(z @ W1 + b1)
        k_gemm128<<<gblk, 256>>>(Ws1 + (size_t)l * DIM * DIM, bs1 + (size_t)l * DIM,
                                 /*asel=*/0, /*csel=*/0, /*mode=*/0,
                                 0u, 0u, n);
        // h = dropout(relu(t @ W2 + b2))
        k_gemm128<<<gblk, 256>>>(Ws2 + (size_t)l * DIM * DIM, bs2 + (size_t)l * DIM,
                                 /*asel=*/1, /*csel=*/1, /*mode=*/1,
                                 dk0[l], dk1[l], n);
    }
    k_linear<<<gblk, 256>>>(Wlin, blin, out, n);
}

// round 5
// speedup vs baseline: 1.1787x; 1.1787x over previous
#include <cuda_runtime.h>
#include <cuda_bf16.h>
#include <cstdint>

#define NMAX 50000
#define EMAX 800000
#define DIM  128
#define ODIM 64
#define PAD  40
#define STRIDE 68   // 32-bit words per 128-col bf16 row (136 bf16 = 272B)

// ---------------- scratch (device globals; no allocations) ----------------
__device__ float g_h[NMAX * DIM];
__device__ float g_z[NMAX * DIM];
__device__ int   g_rowptr[NMAX + 1];
__device__ int   g_cursor[NMAX];
__device__ int   g_srcs[EMAX];

// ---------------- threefry2x32 (exact JAX, partitionable mode) -------------
__host__ __device__ __forceinline__ unsigned rotl32(unsigned x, int r) {
    return (x << r) | (x >> (32 - r));
}

__host__ __device__ __forceinline__ void threefry2x32(
    unsigned k0, unsigned k1, unsigned x0, unsigned x1,
    unsigned& o0, unsigned& o1)
{
    unsigned ks0 = k0, ks1 = k1, ks2 = k0 ^ k1 ^ 0x1BD11BDAu;
    x0 += ks0; x1 += ks1;
#define TFR(r) { x0 += x1; x1 = rotl32(x1, r); x1 ^= x0; }
    TFR(13) TFR(15) TFR(26) TFR(6)   x0 += ks1; x1 += ks2 + 1u;
    TFR(17) TFR(29) TFR(16) TFR(24)  x0 += ks2; x1 += ks0 + 2u;
    TFR(13) TFR(15) TFR(26) TFR(6)   x0 += ks0; x1 += ks1 + 3u;
    TFR(17) TFR(29) TFR(16) TFR(24)  x0 += ks1; x1 += ks2 + 4u;
    TFR(13) TFR(15) TFR(26) TFR(6)   x0 += ks2; x1 += ks0 + 5u;
#undef TFR
    o0 = x0; o1 = x1;
}

__device__ __forceinline__ float dropout_mult(unsigned k0, unsigned k1, unsigned j) {
    unsigned a, b;
    threefry2x32(k0, k1, 0u, j, a, b);
    unsigned bits = a ^ b;
    float u = __uint_as_float((bits >> 9) | 0x3f800000u) - 1.0f;
    return (u < 0.9f) ? (1.0f / 0.9f) : 0.0f;
}

// ---------------- bf16 split helpers ----------------------------------------
__device__ __forceinline__ void bsplit(float x, __nv_bfloat16& h, __nv_bfloat16& l) {
    h = __float2bfloat16(x);
    l = __float2bfloat16(x - __bfloat162float(h));
}

__device__ __forceinline__ unsigned packbf(__nv_bfloat16 lo16, __nv_bfloat16 hi16) {
    // low half = first element (column c), high half = column c+1
    unsigned a = *(unsigned short*)&lo16;
    unsigned b = *(unsigned short*)&hi16;
    return a | (b << 16);
}

// ---------------- mma.sync bf16 m16n8k16 ------------------------------------
#define MMA_BF16(d, a0, a1, a2, a3, b0, b1)                                   \
    asm volatile("mma.sync.aligned.m16n8k16.row.col.f32.bf16.bf16.f32 "       \
        "{%0,%1,%2,%3}, {%4,%5,%6,%7}, {%8,%9}, {%0,%1,%2,%3};"               \
        : "+f"((d)[0]), "+f"((d)[1]), "+f"((d)[2]), "+f"((d)[3])              \
        : "r"(a0), "r"(a1), "r"(a2), "r"(a3), "r"(b0), "r"(b1))

// one 128x128x128 GEMM phase, bf16x3 (AhBh + AhBl + AlBh), acc += A@B^T(stored [n][k])
__device__ __forceinline__ void gemm_phase(
    const unsigned* __restrict__ Ah, const unsigned* __restrict__ Al,
    const unsigned* __restrict__ Bh, const unsigned* __restrict__ Bl,
    float acc[2][8][4], int wr, int wn, int g, int t)
{
#pragma unroll 1
    for (int ks = 0; ks < 8; ks++) {
        const int kw = ks * 8;
#pragma unroll
        for (int p = 0; p < 3; p++) {
            const unsigned* A = (p == 2) ? Al : Ah;
            const unsigned* B = (p == 1) ? Bl : Bh;
            unsigned a[2][4];
#pragma unroll
            for (int mt = 0; mt < 2; mt++) {
                const int r0 = (wr * 32 + mt * 16 + g) * STRIDE + kw + t;
                const int r1 = r0 + 8 * STRIDE;
                a[mt][0] = A[r0];     a[mt][1] = A[r1];
                a[mt][2] = A[r0 + 4]; a[mt][3] = A[r1 + 4];
            }
#pragma unroll
            for (int nt = 0; nt < 8; nt++) {
                const int nb = (wn * 64 + nt * 8 + g) * STRIDE + kw + t;
                const unsigned b0 = B[nb];
                const unsigned b1 = B[nb + 4];
                MMA_BF16(acc[0][nt], a[0][0], a[0][1], a[0][2], a[0][3], b0, b1);
                MMA_BF16(acc[1][nt], a[1][0], a[1][1], a[1][2], a[1][3], b0, b1);
            }
        }
    }
}

// ---------------- CSR build (edge_index int32: row0=src, row1=dst) ---------
__global__ void k_zero(int n) {
    int i = blockIdx.x * blockDim.x + threadIdx.x;
    if (i < n) g_cursor[i] = 0;
}

__global__ void k_hist(const int* __restrict__ ei, int e, int n) {
    int idx = blockIdx.x * blockDim.x + threadIdx.x;
    if (idx < e) {
        int dst = ei[e + idx];
        if ((unsigned)dst < (unsigned)n) atomicAdd(&g_cursor[dst], 1);
    }
}

__global__ void k_scan(int n) {
    __shared__ int wsum[32];
    __shared__ int carry;
    int t = threadIdx.x, lane = t & 31, w = t >> 5;
    if (t == 0) carry = 0;
    __syncthreads();
    for (int base = 0; base < n; base += 1024) {
        int i = base + t;
        int v = (i < n) ? g_cursor[i] : 0;
        int x = v;
#pragma unroll
        for (int off = 1; off < 32; off <<= 1) {
            int y = __shfl_up_sync(0xffffffffu, x, off);
            if (lane >= off) x += y;
        }
        if (lane == 31) wsum[w] = x;
        __syncthreads();
        if (w == 0) {
            int y = wsum[lane];
#pragma unroll
            for (int off = 1; off < 32; off <<= 1) {
                int z2 = __shfl_up_sync(0xffffffffu, y, off);
                if (lane >= off) y += z2;
            }
            wsum[lane] = y;
        }
        __syncthreads();
        int incl = x + (w ? wsum[w - 1] : 0);
        int excl = carry + incl - v;
        if (i < n) { g_rowptr[i] = excl; g_cursor[i] = excl; }
        __syncthreads();
        if (t == 1023) carry += wsum[31];
        __syncthreads();
    }
    if (t == 0) g_rowptr[n] = carry;
}

__global__ void k_scatter(const int* __restrict__ ei, int e, int n) {
    int idx = blockIdx.x * blockDim.x + threadIdx.x;
    if (idx < e) {
        int dst = ei[e + idx];
        int src = ei[idx];
        if ((unsigned)dst < (unsigned)n && (unsigned)src < (unsigned)n) {
            int pos = atomicAdd(&g_cursor[dst], 1);
            if ((unsigned)pos < (unsigned)EMAX) g_srcs[pos] = src;
        }
    }
}

// ---------- aggregation: g_z[i] = base[i] + sum_{src in in(i)} base[src] ----
__global__ __launch_bounds__(DIM) void k_aggregate(
    const float* __restrict__ xin, int use_x, int n)
{
    int i = blockIdx.x;
    if (i >= n) return;
    const float* base = use_x ? xin : g_h;
    int d = threadIdx.x;
    float acc = base[(size_t)i * DIM + d];
    int p = g_rowptr[i];
    const int pe = g_rowptr[i + 1];
    for (; p + 4 <= pe; p += 4) {
        int s0 = g_srcs[p], s1 = g_srcs[p + 1], s2 = g_srcs[p + 2], s3 = g_srcs[p + 3];
        float v0 = base[(size_t)s0 * DIM + d];
        float v1 = base[(size_t)s1 * DIM + d];
        float v2 = base[(size_t)s2 * DIM + d];
        float v3 = base[(size_t)s3 * DIM + d];
        acc += v0; acc += v1; acc += v2; acc += v3;
    }
    for (; p < pe; ++p) acc += base[(size_t)g_srcs[p] * DIM + d];
    g_z[(size_t)i * DIM + d] = acc;
}

// ---------------- fused MLP via mma.sync bf16x3 ------------------------------
// SMEM: [0,512) b1, [512,1024) b2, then 4 tile buffers of 34,816B:
//   Ah, Al (z split, later t split), Wh, Wl (W^T split, restaged W1->W2)
#define BUFW   (128 * STRIDE)                 // words per buffer (8704)
#define SMEM_MMA (1024 + 4 * BUFW * 4)        // 140,288 B

__global__ __launch_bounds__(256, 1) void k_mlp_mma(
    const float* __restrict__ W1g, const float* __restrict__ b1g,
    const float* __restrict__ W2g, const float* __restrict__ b2g,
    unsigned dk0, unsigned dk1, int nrows)
{
    extern __shared__ char smem[];
    float*    sB1 = (float*)smem;
    float*    sB2 = (float*)(smem + 512);
    unsigned* sAh = (unsigned*)(smem + 1024);
    unsigned* sAl = sAh + BUFW;
    unsigned* sWh = sAl + BUFW;
    unsigned* sWl = sWh + BUFW;

    const int tid = threadIdx.x;
    const int wid = tid >> 5;
    const int lane = tid & 31;
    const int wr = wid & 3;        // warp row (32 rows)
    const int wn = wid >> 2;       // warp col (64 cols)
    const int g = lane >> 2;       // group id 0..7
    const int t = lane & 3;        // thread in group

    const int row0 = blockIdx.x * 128;
    const int avail = (nrows - row0 < 128) ? (nrows - row0) : 128;

    if (tid < 128) { sB1[tid] = b1g[tid]; sB2[tid] = b2g[tid]; }

    // stage A = z tile, split hi/lo (4096 float4)
    for (int i = tid; i < 4096; i += 256) {
        int r = i >> 5;
        int c4 = (i & 31) * 4;
        float4 v = make_float4(0.f, 0.f, 0.f, 0.f);
        if (r < avail)
            v = *(const float4*)(g_z + (size_t)(row0 + r) * DIM + c4);
        __nv_bfloat16 hx, lx, hy, ly, hz, lz, hw, lw;
        bsplit(v.x, hx, lx); bsplit(v.y, hy, ly);
        bsplit(v.z, hz, lz); bsplit(v.w, hw, lw);
        int w = r * STRIDE + (c4 >> 1);
        sAh[w]     = packbf(hx, hy);  sAh[w + 1] = packbf(hz, hw);
        sAl[w]     = packbf(lx, ly);  sAl[w + 1] = packbf(lz, lw);
    }
    // stage W1^T split: sW[n][k] <- W1[k][n]
    {
        __nv_bfloat16* ph = (__nv_bfloat16*)sWh;
        __nv_bfloat16* pl = (__nv_bfloat16*)sWl;
        for (int i = tid; i < 16384; i += 256) {
            int k = i >> 7, nn = i & 127;
            __nv_bfloat16 h, l;
            bsplit(W1g[(size_t)k * DIM + nn], h, l);
            ph[nn * (2 * STRIDE) + k] = h;
            pl[nn * (2 * STRIDE) + k] = l;
        }
    }
    __syncthreads();

    float acc[2][8][4];
#pragma unroll
    for (int mt = 0; mt < 2; mt++)
#pragma unroll
        for (int nt = 0; nt < 8; nt++)
#pragma unroll
            for (int q = 0; q < 4; q++) acc[mt][nt][q] = 0.f;

    gemm_phase(sAh, sAl, sWh, sWl, acc, wr, wn, g, t);
    __syncthreads();   // all warps done reading sA/sW

    // epilogue1: t = relu(D1 + b1) -> split back into sAh/sAl; reset acc
#pragma unroll
    for (int mt = 0; mt < 2; mt++) {
        const int r0 = wr * 32 + mt * 16 + g;
#pragma unroll
        for (int nt = 0; nt < 8; nt++) {
            const int c0 = wn * 64 + nt * 8 + 2 * t;
            const float bv0 = sB1[c0], bv1 = sB1[c0 + 1];
            float v00 = fmaxf(acc[mt][nt][0] + bv0, 0.f);
            float v01 = fmaxf(acc[mt][nt][1] + bv1, 0.f);
            float v10 = fmaxf(acc[mt][nt][2] + bv0, 0.f);
            float v11 = fmaxf(acc[mt][nt][3] + bv1, 0.f);
            __nv_bfloat16 h00, l00, h01, l01, h10, l10, h11, l11;
            bsplit(v00, h00, l00); bsplit(v01, h01, l01);
            bsplit(v10, h10, l10); bsplit(v11, h11, l11);
            const int w0 = r0 * STRIDE + (c0 >> 1);
            const int w1 = w0 + 8 * STRIDE;
            sAh[w0] = packbf(h00, h01);  sAl[w0] = packbf(l00, l01);
            sAh[w1] = packbf(h10, h11);  sAl[w1] = packbf(l10, l11);
            acc[mt][nt][0] = 0.f; acc[mt][nt][1] = 0.f;
            acc[mt][nt][2] = 0.f; acc[mt][nt][3] = 0.f;
        }
    }
    // restage W2^T split
    {
        __nv_bfloat16* ph = (__nv_bfloat16*)sWh;
        __nv_bfloat16* pl = (__nv_bfloat16*)sWl;
        for (int i = tid; i < 16384; i += 256) {
            int k = i >> 7, nn = i & 127;
            __nv_bfloat16 h, l;
            bsplit(W2g[(size_t)k * DIM + nn], h, l);
            ph[nn * (2 * STRIDE) + k] = h;
            pl[nn * (2 * STRIDE) + k] = l;
        }
    }
    __syncthreads();

    gemm_phase(sAh, sAl, sWh, sWl, acc, wr, wn, g, t);

    // epilogue2: h = dropout(relu(D2 + b2)) -> g_h
#pragma unroll
    for (int mt = 0; mt < 2; mt++) {
        const int r0 = wr * 32 + mt * 16 + g;
        const int grow0 = row0 + r0;
        const int grow1 = grow0 + 8;
#pragma unroll
        for (int nt = 0; nt < 8; nt++) {
            const int c0 = wn * 64 + nt * 8 + 2 * t;
            const float bv0 = sB2[c0], bv1 = sB2[c0 + 1];
            if (grow0 < nrows) {
                unsigned j = (unsigned)grow0 * (unsigned)DIM + (unsigned)c0;
                float v0 = fmaxf(acc[mt][nt][0] + bv0, 0.f) * dropout_mult(dk0, dk1, j);
                float v1 = fmaxf(acc[mt][nt][1] + bv1, 0.f) * dropout_mult(dk0, dk1, j + 1);
                *(float2*)(g_h + (size_t)grow0 * DIM + c0) = make_float2(v0, v1);
            }
            if (grow1 < nrows) {
                unsigned j = (unsigned)grow1 * (unsigned)DIM + (unsigned)c0;
                float v0 = fmaxf(acc[mt][nt][2] + bv0, 0.f) * dropout_mult(dk0, dk1, j);
                float v1 = fmaxf(acc[mt][nt][3] + bv1, 0.f) * dropout_mult(dk0, dk1, j + 1);
                *(float2*)(g_h + (size_t)grow1 * DIM + c0) = make_float2(v0, v1);
            }
        }
    }
}

// ---------------- final linear: out = g_h @ Wlin + blin (128 -> 64) --------
__global__ __launch_bounds__(256, 1) void k_linear(
    const float* __restrict__ Wg, const float* __restrict__ bg,
    float* __restrict__ out, int nrows)
{
    __shared__ float sA[128 * PAD];
    __shared__ float sW[32 * 64];

    const int tid = threadIdx.x;
    const int tx4 = (tid & 15) * 4;
    const int ty8 = (tid >> 4) * 8;
    const int row0 = blockIdx.x * 128;
    const int avail = (nrows - row0 < 128) ? (nrows - row0) : 128;

    float acc[8][4];
#pragma unroll
    for (int r = 0; r < 8; r++)
#pragma unroll
        for (int c = 0; c < 4; c++) acc[r][c] = 0.0f;

    for (int kc = 0; kc < 128; kc += 32) {
#pragma unroll
        for (int i = tid; i < 1024; i += 256) {
            int r = i >> 3;
            int c4 = (i & 7) * 4;
            float4 v = make_float4(0.f, 0.f, 0.f, 0.f);
            if (r < avail)
                v = *(const float4*)(g_h + (size_t)(row0 + r) * DIM + kc + c4);
            *(float4*)(sA + r * PAD + c4) = v;
        }
#pragma unroll
        for (int i = tid; i < 512; i += 256) {
            int r = i >> 4;
            int c4 = (i & 15) * 4;
            *(float4*)(sW + r * 64 + c4) =
                *(const float4*)(Wg + (size_t)(kc + r) * ODIM + c4);
        }
        __syncthreads();

#pragma unroll
        for (int k = 0; k < 32; k += 4) {
            float4 a[8];
#pragma unroll
            for (int r = 0; r < 8; r++)
                a[r] = *(const float4*)(sA + (ty8 + r) * PAD + k);
#pragma unroll
            for (int kk = 0; kk < 4; kk++) {
                const float4 w = *(const float4*)(sW + (k + kk) * 64 + tx4);
#pragma unroll
                for (int r = 0; r < 8; r++) {
                    const float av = (kk == 0) ? a[r].x : (kk == 1) ? a[r].y
                                   : (kk == 2) ? a[r].z : a[r].w;
                    acc[r][0] = fmaf(av, w.x, acc[r][0]);
                    acc[r][1] = fmaf(av, w.y, acc[r][1]);
                    acc[r][2] = fmaf(av, w.z, acc[r][2]);
                    acc[r][3] = fmaf(av, w.w, acc[r][3]);
                }
            }
        }
        __syncthreads();
    }

    float b[4];
#pragma unroll
    for (int c = 0; c < 4; c++) b[c] = bg[tx4 + c];
#pragma unroll
    for (int r = 0; r < 8; r++) {
        int grow = row0 + ty8 + r;
        if (grow >= nrows) break;
        *(float4*)(out + (size_t)grow * ODIM + tx4) =
            make_float4(acc[r][0] + b[0], acc[r][1] + b[1],
                        acc[r][2] + b[2], acc[r][3] + b[3]);
    }
}

// ---------------- launch ----------------------------------------------------
extern "C" void kernel_launch(void* const* d_in, const int* in_sizes, int n_in,
                              void* d_out, int out_size)
{
    const float* x    = (const float*)d_in[0];
    const int*   ei   = (const int*)d_in[1];
    const float* Ws1  = (const float*)d_in[2];
    const float* bs1  = (const float*)d_in[3];
    const float* Ws2  = (const float*)d_in[4];
    const float* bs2  = (const float*)d_in[5];
    const float* Wlin = (const float*)d_in[6];
    const float* blin = (const float*)d_in[7];
    float*       out  = (float*)d_out;

    const int n = in_sizes[0] / DIM;
    const int e = in_sizes[1] / 2;
    if (n > NMAX || e > EMAX || n <= 0) return;

    cudaFuncSetAttribute(k_mlp_mma, cudaFuncAttributeMaxDynamicSharedMemorySize, SMEM_MMA);

    // dropout keys: jax.random.split(jax.random.key(42), 3), partitionable fold
    unsigned dk0[3], dk1[3];
    for (int l = 0; l < 3; l++)
        threefry2x32(0u, 42u, 0u, (unsigned)l, dk0[l], dk1[l]);

    k_zero   <<<(n + 255) / 256, 256>>>(n);
    k_hist   <<<(e + 255) / 256, 256>>>(ei, e, n);
    k_scan   <<<1, 1024>>>(n);
    k_scatter<<<(e + 255) / 256, 256>>>(ei, e, n);

    const int gblk = (n + 127) / 128;
    for (int l = 0; l < 3; l++) {
        k_aggregate<<<n, DIM>>>(x, l == 0 ? 1 : 0, n);
        k_mlp_mma<<<gblk, 256, SMEM_MMA>>>(
            Ws1 + (size_t)l * DIM * DIM, bs1 + (size_t)l * DIM,
            Ws2 + (size_t)l * DIM * DIM, bs2 + (size_t)l * DIM,
            dk0[l], dk1[l], n);
    }
    k_linear<<<gblk, 256>>>(Wlin, blin, out, n);
}

// round 6
// speedup vs baseline: 1.6606x; 1.4089x over previous
#include <cuda_runtime.h>
#include <cuda_bf16.h>
#include <cstdint>

#define NMAX 50000
#define EMAX 800000
#define DIM  128
#define ODIM 64
#define PAD  40
#define STRIDE 68   // A-buffer words per 128-col row (136 bf16 = 272B)
#define WSTR   36   // W-chunk buffer words per row (64 k = 32 words + 4 pad)

// ---------------- scratch (device globals; no allocations) ----------------
__device__ float    g_h[NMAX * DIM];        // layer output (float)
__device__ unsigned g_ah[NMAX * 64];        // aggregated z, bf16-hi packed
__device__ unsigned g_al[NMAX * 64];        // aggregated z, bf16-lo packed
__device__ unsigned g_wsph[3 * 2 * 2 * 4096];  // pre-split W hi (l,m,chunk,n,w)
__device__ unsigned g_wspl[3 * 2 * 2 * 4096];  // pre-split W lo
__device__ int      g_rowptr[NMAX + 1];
__device__ int      g_cursor[NMAX];
__device__ int      g_srcs[EMAX];

// ---------------- threefry2x32 (exact JAX, partitionable mode) -------------
__host__ __device__ __forceinline__ unsigned rotl32(unsigned x, int r) {
    return (x << r) | (x >> (32 - r));
}

__host__ __device__ __forceinline__ void threefry2x32(
    unsigned k0, unsigned k1, unsigned x0, unsigned x1,
    unsigned& o0, unsigned& o1)
{
    unsigned ks0 = k0, ks1 = k1, ks2 = k0 ^ k1 ^ 0x1BD11BDAu;
    x0 += ks0; x1 += ks1;
#define TFR(r) { x0 += x1; x1 = rotl32(x1, r); x1 ^= x0; }
    TFR(13) TFR(15) TFR(26) TFR(6)   x0 += ks1; x1 += ks2 + 1u;
    TFR(17) TFR(29) TFR(16) TFR(24)  x0 += ks2; x1 += ks0 + 2u;
    TFR(13) TFR(15) TFR(26) TFR(6)   x0 += ks0; x1 += ks1 + 3u;
    TFR(17) TFR(29) TFR(16) TFR(24)  x0 += ks1; x1 += ks2 + 4u;
    TFR(13) TFR(15) TFR(26) TFR(6)   x0 += ks2; x1 += ks0 + 5u;
#undef TFR
    o0 = x0; o1 = x1;
}

__device__ __forceinline__ float dropout_mult(unsigned k0, unsigned k1, unsigned j) {
    unsigned a, b;
    threefry2x32(k0, k1, 0u, j, a, b);
    unsigned bits = a ^ b;
    float u = __uint_as_float((bits >> 9) | 0x3f800000u) - 1.0f;
    return (u < 0.9f) ? (1.0f / 0.9f) : 0.0f;
}

// ---------------- bf16 split helpers ----------------------------------------
__device__ __forceinline__ void bsplit(float x, __nv_bfloat16& h, __nv_bfloat16& l) {
    h = __float2bfloat16(x);
    l = __float2bfloat16(x - __bfloat162float(h));
}

__device__ __forceinline__ unsigned packbf(__nv_bfloat16 lo16, __nv_bfloat16 hi16) {
    unsigned a = *(unsigned short*)&lo16;
    unsigned b = *(unsigned short*)&hi16;
    return a | (b << 16);
}

// ---------------- mma.sync bf16 m16n8k16 ------------------------------------
#define MMA_BF16(d, a0, a1, a2, a3, b0, b1)                                   \
    asm volatile("mma.sync.aligned.m16n8k16.row.col.f32.bf16.bf16.f32 "       \
        "{%0,%1,%2,%3}, {%4,%5,%6,%7}, {%8,%9}, {%0,%1,%2,%3};"               \
        : "+f"((d)[0]), "+f"((d)[1]), "+f"((d)[2]), "+f"((d)[3])              \
        : "r"(a0), "r"(a1), "r"(a2), "r"(a3), "r"(b0), "r"(b1))

// one 128x128x64 GEMM chunk, bf16x3; A words at base offset akw0, B chunk-local
__device__ __forceinline__ void gemm_chunk(
    const unsigned* __restrict__ Ah, const unsigned* __restrict__ Al,
    const unsigned* __restrict__ Bh, const unsigned* __restrict__ Bl,
    float acc[2][8][4], int wr, int wn, int g, int t, int akw0)
{
#pragma unroll 1
    for (int ks = 0; ks < 4; ks++) {
        const int kw = ks * 8;
#pragma unroll
        for (int p = 0; p < 3; p++) {
            const unsigned* A = (p == 2) ? Al : Ah;
            const unsigned* B = (p == 1) ? Bl : Bh;
            unsigned a[2][4];
#pragma unroll
            for (int mt = 0; mt < 2; mt++) {
                const int r0 = (wr * 32 + mt * 16 + g) * STRIDE + akw0 + kw + t;
                const int r1 = r0 + 8 * STRIDE;
                a[mt][0] = A[r0];     a[mt][1] = A[r1];
                a[mt][2] = A[r0 + 4]; a[mt][3] = A[r1 + 4];
            }
#pragma unroll
            for (int nt = 0; nt < 8; nt++) {
                const int nb = (wn * 64 + nt * 8 + g) * WSTR + kw + t;
                const unsigned b0 = B[nb];
                const unsigned b1 = B[nb + 4];
                MMA_BF16(acc[0][nt], a[0][0], a[0][1], a[0][2], a[0][3], b0, b1);
                MMA_BF16(acc[1][nt], a[1][0], a[1][1], a[1][2], a[1][3], b0, b1);
            }
        }
    }
}

// ---------------- pre-split weights into packed blocked layout --------------
// idx = l*16384 + m*8192 + c*4096 + nn*32 + w ;  k0 = c*64 + 2w
__global__ void k_split_w(const float* __restrict__ Ws1,
                          const float* __restrict__ Ws2)
{
    int idx = blockIdx.x * blockDim.x + threadIdx.x;
    if (idx >= 3 * 2 * 2 * 4096) return;
    int w  = idx & 31;
    int nn = (idx >> 5) & 127;
    int c  = (idx >> 12) & 1;
    int m  = (idx >> 13) & 1;
    int l  = idx >> 14;
    const float* W = (m == 0 ? Ws1 : Ws2) + (size_t)l * DIM * DIM;
    int k0 = c * 64 + 2 * w;
    float w0 = W[(size_t)k0 * DIM + nn];
    float w1 = W[(size_t)(k0 + 1) * DIM + nn];
    __nv_bfloat16 h0, l0, h1, l1;
    bsplit(w0, h0, l0); bsplit(w1, h1, l1);
    g_wsph[idx] = packbf(h0, h1);
    g_wspl[idx] = packbf(l0, l1);
}

// ---------------- CSR build (edge_index int32: row0=src, row1=dst) ---------
__global__ void k_zero(int n) {
    int i = blockIdx.x * blockDim.x + threadIdx.x;
    if (i < n) g_cursor[i] = 0;
}

__global__ void k_hist(const int* __restrict__ ei, int e, int n) {
    int idx = blockIdx.x * blockDim.x + threadIdx.x;
    if (idx < e) {
        int dst = ei[e + idx];
        if ((unsigned)dst < (unsigned)n) atomicAdd(&g_cursor[dst], 1);
    }
}

__global__ void k_scan(int n) {
    __shared__ int wsum[32];
    __shared__ int carry;
    int t = threadIdx.x, lane = t & 31, w = t >> 5;
    if (t == 0) carry = 0;
    __syncthreads();
    for (int base = 0; base < n; base += 1024) {
        int i = base + t;
        int v = (i < n) ? g_cursor[i] : 0;
        int x = v;
#pragma unroll
        for (int off = 1; off < 32; off <<= 1) {
            int y = __shfl_up_sync(0xffffffffu, x, off);
            if (lane >= off) x += y;
        }
        if (lane == 31) wsum[w] = x;
        __syncthreads();
        if (w == 0) {
            int y = wsum[lane];
#pragma unroll
            for (int off = 1; off < 32; off <<= 1) {
                int z2 = __shfl_up_sync(0xffffffffu, y, off);
                if (lane >= off) y += z2;
            }
            wsum[lane] = y;
        }
        __syncthreads();
        int incl = x + (w ? wsum[w - 1] : 0);
        int excl = carry + incl - v;
        if (i < n) { g_rowptr[i] = excl; g_cursor[i] = excl; }
        __syncthreads();
        if (t == 1023) carry += wsum[31];
        __syncthreads();
    }
    if (t == 0) g_rowptr[n] = carry;
}

__global__ void k_scatter(const int* __restrict__ ei, int e, int n) {
    int idx = blockIdx.x * blockDim.x + threadIdx.x;
    if (idx < e) {
        int dst = ei[e + idx];
        int src = ei[idx];
        if ((unsigned)dst < (unsigned)n && (unsigned)src < (unsigned)n) {
            int pos = atomicAdd(&g_cursor[dst], 1);
            if ((unsigned)pos < (unsigned)EMAX) g_srcs[pos] = src;
        }
    }
}

// ---------- aggregation + split: packed bf16 hi/lo of (base[i] + sum nbrs) --
__global__ __launch_bounds__(64) void k_aggregate(
    const float* __restrict__ xin, int use_x, int n)
{
    int i = blockIdx.x;
    if (i >= n) return;
    const float* base = use_x ? xin : g_h;
    const float2* b2 = (const float2*)base;
    int d = threadIdx.x;               // 0..63, two columns per thread
    float2 acc = b2[(size_t)i * 64 + d];
    int p = g_rowptr[i];
    const int pe = g_rowptr[i + 1];
    for (; p + 4 <= pe; p += 4) {
        int s0 = g_srcs[p], s1 = g_srcs[p + 1], s2 = g_srcs[p + 2], s3 = g_srcs[p + 3];
        float2 v0 = b2[(size_t)s0 * 64 + d];
        float2 v1 = b2[(size_t)s1 * 64 + d];
        float2 v2 = b2[(size_t)s2 * 64 + d];
        float2 v3 = b2[(size_t)s3 * 64 + d];
        acc.x += v0.x; acc.y += v0.y;
        acc.x += v1.x; acc.y += v1.y;
        acc.x += v2.x; acc.y += v2.y;
        acc.x += v3.x; acc.y += v3.y;
    }
    for (; p < pe; ++p) {
        float2 v = b2[(size_t)g_srcs[p] * 64 + d];
        acc.x += v.x; acc.y += v.y;
    }
    __nv_bfloat16 h0, l0, h1, l1;
    bsplit(acc.x, h0, l0); bsplit(acc.y, h1, l1);
    g_ah[(size_t)i * 64 + d] = packbf(h0, h1);
    g_al[(size_t)i * 64 + d] = packbf(l0, l1);
}

// ---------------- fused MLP via mma.sync bf16x3 ------------------------------
// SMEM: [0,512) b1, [512,1024) b2, Ah/Al (34,816B each), Wh/Wl (18,432B each)
#define BUFW     (128 * STRIDE)             // 8704 words
#define WBUF     (128 * WSTR)               // 4608 words
#define SMEM_MMA (1024 + 2 * BUFW * 4 + 2 * WBUF * 4)   // 107,520 B

__global__ __launch_bounds__(256) void k_mlp_mma(
    const float* __restrict__ b1g, const float* __restrict__ b2g,
    int lidx, unsigned dk0, unsigned dk1, int nrows)
{
    extern __shared__ char smem[];
    float*    sB1 = (float*)smem;
    float*    sB2 = (float*)(smem + 512);
    unsigned* sAh = (unsigned*)(smem + 1024);
    unsigned* sAl = sAh + BUFW;
    unsigned* sWh = sAl + BUFW;
    unsigned* sWl = sWh + WBUF;

    const int tid = threadIdx.x;
    const int wid = tid >> 5;
    const int lane = tid & 31;
    const int wr = wid & 3;
    const int wn = wid >> 2;
    const int g = lane >> 2;
    const int t = lane & 3;

    const int row0 = blockIdx.x * 128;
    const int avail = (nrows - row0 < 128) ? (nrows - row0) : 128;

    if (tid < 128) { sB1[tid] = b1g[tid]; sB2[tid] = b2g[tid]; }

    // stage A tile: straight packed copy (2048 uint4 per buffer pair)
    for (int i = tid; i < 2048; i += 256) {
        int r  = i >> 4;
        int w4 = (i & 15) * 4;
        uint4 vh = make_uint4(0, 0, 0, 0), vl = make_uint4(0, 0, 0, 0);
        if (r < avail) {
            vh = *(const uint4*)(g_ah + (size_t)(row0 + r) * 64 + w4);
            vl = *(const uint4*)(g_al + (size_t)(row0 + r) * 64 + w4);
        }
        *(uint4*)(sAh + r * STRIDE + w4) = vh;
        *(uint4*)(sAl + r * STRIDE + w4) = vl;
    }

    float acc[2][8][4];
#pragma unroll
    for (int mt = 0; mt < 2; mt++)
#pragma unroll
        for (int nt = 0; nt < 8; nt++)
#pragma unroll
            for (int q = 0; q < 4; q++) acc[mt][nt][q] = 0.f;

    // ---------------- GEMM1: two W1 chunks ----------------------------------
#pragma unroll 1
    for (int c = 0; c < 2; c++) {
        const unsigned* gh = g_wsph + ((lidx * 2 + 0) * 2 + c) * 4096;
        const unsigned* gl = g_wspl + ((lidx * 2 + 0) * 2 + c) * 4096;
        for (int i = tid; i < 1024; i += 256) {
            int nn = i >> 3;
            int w4 = (i & 7) * 4;
            *(uint4*)(sWh + nn * WSTR + w4) = *(const uint4*)(gh + nn * 32 + w4);
            *(uint4*)(sWl + nn * WSTR + w4) = *(const uint4*)(gl + nn * 32 + w4);
        }
        __syncthreads();
        gemm_chunk(sAh, sAl, sWh, sWl, acc, wr, wn, g, t, c * 32);
        __syncthreads();
    }

    // epilogue1: t = relu(D1 + b1) -> split back into sAh/sAl; reset acc
#pragma unroll
    for (int mt = 0; mt < 2; mt++) {
        const int r0 = wr * 32 + mt * 16 + g;
#pragma unroll
        for (int nt = 0; nt < 8; nt++) {
            const int c0 = wn * 64 + nt * 8 + 2 * t;
            const float bv0 = sB1[c0], bv1 = sB1[c0 + 1];
            float v00 = fmaxf(acc[mt][nt][0] + bv0, 0.f);
            float v01 = fmaxf(acc[mt][nt][1] + bv1, 0.f);
            float v10 = fmaxf(acc[mt][nt][2] + bv0, 0.f);
            float v11 = fmaxf(acc[mt][nt][3] + bv1, 0.f);
            __nv_bfloat16 h00, l00, h01, l01, h10, l10, h11, l11;
            bsplit(v00, h00, l00); bsplit(v01, h01, l01);
            bsplit(v10, h10, l10); bsplit(v11, h11, l11);
            const int w0 = r0 * STRIDE + (c0 >> 1);
            const int w1 = w0 + 8 * STRIDE;
            sAh[w0] = packbf(h00, h01);  sAl[w0] = packbf(l00, l01);
            sAh[w1] = packbf(h10, h11);  sAl[w1] = packbf(l10, l11);
            acc[mt][nt][0] = 0.f; acc[mt][nt][1] = 0.f;
            acc[mt][nt][2] = 0.f; acc[mt][nt][3] = 0.f;
        }
    }
    __syncthreads();

    // ---------------- GEMM2: two W2 chunks ----------------------------------
#pragma unroll 1
    for (int c = 0; c < 2; c++) {
        const unsigned* gh = g_wsph + ((lidx * 2 + 1) * 2 + c) * 4096;
        const unsigned* gl = g_wspl + ((lidx * 2 + 1) * 2 + c) * 4096;
        for (int i = tid; i < 1024; i += 256) {
            int nn = i >> 3;
            int w4 = (i & 7) * 4;
            *(uint4*)(sWh + nn * WSTR + w4) = *(const uint4*)(gh + nn * 32 + w4);
            *(uint4*)(sWl + nn * WSTR + w4) = *(const uint4*)(gl + nn * 32 + w4);
        }
        __syncthreads();
        gemm_chunk(sAh, sAl, sWh, sWl, acc, wr, wn, g, t, c * 32);
        __syncthreads();
    }

    // epilogue2: h = dropout(relu(D2 + b2)) -> g_h
#pragma unroll
    for (int mt = 0; mt < 2; mt++) {
        const int r0 = wr * 32 + mt * 16 + g;
        const int grow0 = row0 + r0;
        const int grow1 = grow0 + 8;
#pragma unroll
        for (int nt = 0; nt < 8; nt++) {
            const int c0 = wn * 64 + nt * 8 + 2 * t;
            const float bv0 = sB2[c0], bv1 = sB2[c0 + 1];
            if (grow0 < nrows) {
                unsigned j = (unsigned)grow0 * (unsigned)DIM + (unsigned)c0;
                float v0 = fmaxf(acc[mt][nt][0] + bv0, 0.f) * dropout_mult(dk0, dk1, j);
                float v1 = fmaxf(acc[mt][nt][1] + bv1, 0.f) * dropout_mult(dk0, dk1, j + 1);
                *(float2*)(g_h + (size_t)grow0 * DIM + c0) = make_float2(v0, v1);
            }
            if (grow1 < nrows) {
                unsigned j = (unsigned)grow1 * (unsigned)DIM + (unsigned)c0;
                float v0 = fmaxf(acc[mt][nt][2] + bv0, 0.f) * dropout_mult(dk0, dk1, j);
                float v1 = fmaxf(acc[mt][nt][3] + bv1, 0.f) * dropout_mult(dk0, dk1, j + 1);
                *(float2*)(g_h + (size_t)grow1 * DIM + c0) = make_float2(v0, v1);
            }
        }
    }
}

// ---------------- final linear: out = g_h @ Wlin + blin (128 -> 64) --------
__global__ __launch_bounds__(256, 1) void k_linear(
    const float* __restrict__ Wg, const float* __restrict__ bg,
    float* __restrict__ out, int nrows)
{
    __shared__ float sA[128 * PAD];
    __shared__ float sW[32 * 64];

    const int tid = threadIdx.x;
    const int tx4 = (tid & 15) * 4;
    const int ty8 = (tid >> 4) * 8;
    const int row0 = blockIdx.x * 128;
    const int avail = (nrows - row0 < 128) ? (nrows - row0) : 128;

    float acc[8][4];
#pragma unroll
    for (int r = 0; r < 8; r++)
#pragma unroll
        for (int c = 0; c < 4; c++) acc[r][c] = 0.0f;

    for (int kc = 0; kc < 128; kc += 32) {
#pragma unroll
        for (int i = tid; i < 1024; i += 256) {
            int r = i >> 3;
            int c4 = (i & 7) * 4;
            float4 v = make_float4(0.f, 0.f, 0.f, 0.f);
            if (r < avail)
                v = *(const float4*)(g_h + (size_t)(row0 + r) * DIM + kc + c4);
            *(float4*)(sA + r * PAD + c4) = v;
        }
#pragma unroll
        for (int i = tid; i < 512; i += 256) {
            int r = i >> 4;
            int c4 = (i & 15) * 4;
            *(float4*)(sW + r * 64 + c4) =
                *(const float4*)(Wg + (size_t)(kc + r) * ODIM + c4);
        }
        __syncthreads();

#pragma unroll
        for (int k = 0; k < 32; k += 4) {
            float4 a[8];
#pragma unroll
            for (int r = 0; r < 8; r++)
                a[r] = *(const float4*)(sA + (ty8 + r) * PAD + k);
#pragma unroll
            for (int kk = 0; kk < 4; kk++) {
                const float4 w = *(const float4*)(sW + (k + kk) * 64 + tx4);
#pragma unroll
                for (int r = 0; r < 8; r++) {
                    const float av = (kk == 0) ? a[r].x : (kk == 1) ? a[r].y
                                   : (kk == 2) ? a[r].z : a[r].w;
                    acc[r][0] = fmaf(av, w.x, acc[r][0]);
                    acc[r][1] = fmaf(av, w.y, acc[r][1]);
                    acc[r][2] = fmaf(av, w.z, acc[r][2]);
                    acc[r][3] = fmaf(av, w.w, acc[r][3]);
                }
            }
        }
        __syncthreads();
    }

    float b[4];
#pragma unroll
    for (int c = 0; c < 4; c++) b[c] = bg[tx4 + c];
#pragma unroll
    for (int r = 0; r < 8; r++) {
        int grow = row0 + ty8 + r;
        if (grow >= nrows) break;
        *(float4*)(out + (size_t)grow * ODIM + tx4) =
            make_float4(acc[r][0] + b[0], acc[r][1] + b[1],
                        acc[r][2] + b[2], acc[r][3] + b[3]);
    }
}

// ---------------- launch ----------------------------------------------------
extern "C" void kernel_launch(void* const* d_in, const int* in_sizes, int n_in,
                              void* d_out, int out_size)
{
    const float* x    = (const float*)d_in[0];
    const int*   ei   = (const int*)d_in[1];
    const float* Ws1  = (const float*)d_in[2];
    const float* bs1  = (const float*)d_in[3];
    const float* Ws2  = (const float*)d_in[4];
    const float* bs2  = (const float*)d_in[5];
    const float* Wlin = (const float*)d_in[6];
    const float* blin = (const float*)d_in[7];
    float*       out  = (float*)d_out;

    const int n = in_sizes[0] / DIM;
    const int e = in_sizes[1] / 2;
    if (n > NMAX || e > EMAX || n <= 0) return;

    cudaFuncSetAttribute(k_mlp_mma, cudaFuncAttributeMaxDynamicSharedMemorySize, SMEM_MMA);

    unsigned dk0[3], dk1[3];
    for (int l = 0; l < 3; l++)
        threefry2x32(0u, 42u, 0u, (unsigned)l, dk0[l], dk1[l]);

    // one-time per launch: pre-split weights + CSR build
    k_split_w<<<(3 * 2 * 2 * 4096 + 255) / 256, 256>>>(Ws1, Ws2);
    k_zero   <<<(n + 255) / 256, 256>>>(n);
    k_hist   <<<(e + 255) / 256, 256>>>(ei, e, n);
    k_scan   <<<1, 1024>>>(n);
    k_scatter<<<(e + 255) / 256, 256>>>(ei, e, n);

    const int gblk = (n + 127) / 128;
    for (int l = 0; l < 3; l++) {
        k_aggregate<<<n, 64>>>(x, l == 0 ? 1 : 0, n);
        k_mlp_mma<<<gblk, 256, SMEM_MMA>>>(
            bs1 + (size_t)l * DIM, bs2 + (size_t)l * DIM,
            l, dk0[l], dk1[l], n);
    }
    k_linear<<<gblk, 256>>>(Wlin, blin, out, n);
}

// round 7
// speedup vs baseline: 1.9157x; 1.1536x over previous
#include <cuda_runtime.h>
#include <cuda_bf16.h>
#include <cstdint>

#define NMAX 50000
#define EMAX 800000
#define DIM  128
#define ODIM 64
#define PAD  40
#define STRIDE 68   // A-buffer words per 128-col row (136 bf16 = 272B)
#define WSTR   36   // W-chunk buffer words per row (64 k = 32 words + 4 pad)
#define SCANB  4096 // elements per scan block
#define MAXSB  64   // max scan blocks (n <= 262144)

// ---------------- scratch (device globals; no allocations) ----------------
__device__ float    g_h[NMAX * DIM];        // layer output (float)
__device__ unsigned g_ah[NMAX * 64];        // aggregated z, bf16-hi packed
__device__ unsigned g_al[NMAX * 64];        // aggregated z, bf16-lo packed
__device__ unsigned g_wsph[3 * 2 * 2 * 4096];  // pre-split W hi (l,m,chunk,n,w)
__device__ unsigned g_wspl[3 * 2 * 2 * 4096];  // pre-split W lo
__device__ int      g_rowptr[NMAX + 1];
__device__ int      g_cursor[NMAX];
__device__ int      g_srcs[EMAX];
__device__ int      g_bsum[MAXSB];

// ---------------- threefry2x32 (exact JAX, partitionable mode) -------------
__host__ __device__ __forceinline__ unsigned rotl32(unsigned x, int r) {
    return (x << r) | (x >> (32 - r));
}

__host__ __device__ __forceinline__ void threefry2x32(
    unsigned k0, unsigned k1, unsigned x0, unsigned x1,
    unsigned& o0, unsigned& o1)
{
    unsigned ks0 = k0, ks1 = k1, ks2 = k0 ^ k1 ^ 0x1BD11BDAu;
    x0 += ks0; x1 += ks1;
#define TFR(r) { x0 += x1; x1 = rotl32(x1, r); x1 ^= x0; }
    TFR(13) TFR(15) TFR(26) TFR(6)   x0 += ks1; x1 += ks2 + 1u;
    TFR(17) TFR(29) TFR(16) TFR(24)  x0 += ks2; x1 += ks0 + 2u;
    TFR(13) TFR(15) TFR(26) TFR(6)   x0 += ks0; x1 += ks1 + 3u;
    TFR(17) TFR(29) TFR(16) TFR(24)  x0 += ks1; x1 += ks2 + 4u;
    TFR(13) TFR(15) TFR(26) TFR(6)   x0 += ks2; x1 += ks0 + 5u;
#undef TFR
    o0 = x0; o1 = x1;
}

__device__ __forceinline__ float dropout_mult(unsigned k0, unsigned k1, unsigned j) {
    unsigned a, b;
    threefry2x32(k0, k1, 0u, j, a, b);
    unsigned bits = a ^ b;
    float u = __uint_as_float((bits >> 9) | 0x3f800000u) - 1.0f;
    return (u < 0.9f) ? (1.0f / 0.9f) : 0.0f;
}

// ---------------- bf16 split helpers ----------------------------------------
__device__ __forceinline__ void bsplit(float x, __nv_bfloat16& h, __nv_bfloat16& l) {
    h = __float2bfloat16(x);
    l = __float2bfloat16(x - __bfloat162float(h));
}

__device__ __forceinline__ unsigned packbf(__nv_bfloat16 lo16, __nv_bfloat16 hi16) {
    unsigned a = *(unsigned short*)&lo16;
    unsigned b = *(unsigned short*)&hi16;
    return a | (b << 16);
}

// ---------------- mma.sync bf16 m16n8k16 ------------------------------------
#define MMA_BF16(d, a0, a1, a2, a3, b0, b1)                                   \
    asm volatile("mma.sync.aligned.m16n8k16.row.col.f32.bf16.bf16.f32 "       \
        "{%0,%1,%2,%3}, {%4,%5,%6,%7}, {%8,%9}, {%0,%1,%2,%3};"               \
        : "+f"((d)[0]), "+f"((d)[1]), "+f"((d)[2]), "+f"((d)[3])              \
        : "r"(a0), "r"(a1), "r"(a2), "r"(a3), "r"(b0), "r"(b1))

__device__ __forceinline__ void gemm_chunk(
    const unsigned* __restrict__ Ah, const unsigned* __restrict__ Al,
    const unsigned* __restrict__ Bh, const unsigned* __restrict__ Bl,
    float acc[2][8][4], int wr, int wn, int g, int t, int akw0)
{
#pragma unroll 1
    for (int ks = 0; ks < 4; ks++) {
        const int kw = ks * 8;
#pragma unroll
        for (int p = 0; p < 3; p++) {
            const unsigned* A = (p == 2) ? Al : Ah;
            const unsigned* B = (p == 1) ? Bl : Bh;
            unsigned a[2][4];
#pragma unroll
            for (int mt = 0; mt < 2; mt++) {
                const int r0 = (wr * 32 + mt * 16 + g) * STRIDE + akw0 + kw + t;
                const int r1 = r0 + 8 * STRIDE;
                a[mt][0] = A[r0];     a[mt][1] = A[r1];
                a[mt][2] = A[r0 + 4]; a[mt][3] = A[r1 + 4];
            }
#pragma unroll
            for (int nt = 0; nt < 8; nt++) {
                const int nb = (wn * 64 + nt * 8 + g) * WSTR + kw + t;
                const unsigned b0 = B[nb];
                const unsigned b1 = B[nb + 4];
                MMA_BF16(acc[0][nt], a[0][0], a[0][1], a[0][2], a[0][3], b0, b1);
                MMA_BF16(acc[1][nt], a[1][0], a[1][1], a[1][2], a[1][3], b0, b1);
            }
        }
    }
}

// ---------------- pre-split weights into packed blocked layout --------------
__global__ void k_split_w(const float* __restrict__ Ws1,
                          const float* __restrict__ Ws2)
{
    int idx = blockIdx.x * blockDim.x + threadIdx.x;
    if (idx >= 3 * 2 * 2 * 4096) return;
    int w  = idx & 31;
    int nn = (idx >> 5) & 127;
    int c  = (idx >> 12) & 1;
    int m  = (idx >> 13) & 1;
    int l  = idx >> 14;
    const float* W = (m == 0 ? Ws1 : Ws2) + (size_t)l * DIM * DIM;
    int k0 = c * 64 + 2 * w;
    float w0 = W[(size_t)k0 * DIM + nn];
    float w1 = W[(size_t)(k0 + 1) * DIM + nn];
    __nv_bfloat16 h0, l0, h1, l1;
    bsplit(w0, h0, l0); bsplit(w1, h1, l1);
    g_wsph[idx] = packbf(h0, h1);
    g_wspl[idx] = packbf(l0, l1);
}

// ---------------- CSR build (edge_index int32: row0=src, row1=dst) ---------
__global__ void k_zero(int n) {
    int i = blockIdx.x * blockDim.x + threadIdx.x;
    if (i < n) g_cursor[i] = 0;
}

__global__ void k_hist(const int* __restrict__ ei, int e, int n) {
    int idx = blockIdx.x * blockDim.x + threadIdx.x;
    if (idx < e) {
        int dst = ei[e + idx];
        if ((unsigned)dst < (unsigned)n) atomicAdd(&g_cursor[dst], 1);
    }
}

// pass 1: per-block exclusive scan of g_cursor -> g_rowptr (local), totals -> g_bsum
__global__ __launch_bounds__(1024) void k_scan1(int n) {
    __shared__ int wsum[32];
    const int t = threadIdx.x, lane = t & 31, w = t >> 5;
    const int base = blockIdx.x * SCANB + t * 4;
    int v0 = 0, v1 = 0, v2 = 0, v3 = 0;
    if (base + 0 < n) v0 = g_cursor[base + 0];
    if (base + 1 < n) v1 = g_cursor[base + 1];
    if (base + 2 < n) v2 = g_cursor[base + 2];
    if (base + 3 < n) v3 = g_cursor[base + 3];
    int s = v0 + v1 + v2 + v3;
    int x = s;
#pragma unroll
    for (int off = 1; off < 32; off <<= 1) {
        int y = __shfl_up_sync(0xffffffffu, x, off);
        if (lane >= off) x += y;
    }
    if (lane == 31) wsum[w] = x;
    __syncthreads();
    if (w == 0) {
        int y = (lane < 32) ? wsum[lane] : 0;
#pragma unroll
        for (int off = 1; off < 32; off <<= 1) {
            int z2 = __shfl_up_sync(0xffffffffu, y, off);
            if (lane >= off) y += z2;
        }
        wsum[lane] = y;
    }
    __syncthreads();
    int excl = (x - s) + (w ? wsum[w - 1] : 0);
    if (base + 0 < n) g_rowptr[base + 0] = excl;
    if (base + 1 < n) g_rowptr[base + 1] = excl + v0;
    if (base + 2 < n) g_rowptr[base + 2] = excl + v0 + v1;
    if (base + 3 < n) g_rowptr[base + 3] = excl + v0 + v1 + v2;
    if (t == 1023) g_bsum[blockIdx.x] = wsum[31];
}

// pass 2: exclusive scan of block totals (single warp); grand total -> rowptr[n]
__global__ void k_scan2(int nblk, int n) {
    int lane = threadIdx.x;
    int v = (lane < nblk) ? g_bsum[lane] : 0;
    int x = v;
#pragma unroll
    for (int off = 1; off < 32; off <<= 1) {
        int y = __shfl_up_sync(0xffffffffu, x, off);
        if (lane >= off) x += y;
    }
    // supports nblk <= 64 via second pass over two warps' worth
    if (nblk > 32) {
        // handle 33..64: lane 0..31 covers first 32; do a simple loop fixup
        if (lane == 0) {
            int run = 0;
            for (int i = 0; i < nblk; i++) { int t = g_bsum[i]; g_bsum[i] = run; run += t; }
            g_rowptr[n] = run;
        }
        return;
    }
    if (lane < nblk) g_bsum[lane] = x - v;
    if (lane == nblk - 1) g_rowptr[n] = x;
}

// pass 3: add block offsets; materialize cursor
__global__ __launch_bounds__(1024) void k_scan3(int n) {
    int i = blockIdx.x * SCANB + threadIdx.x * 4;
    int off = g_bsum[blockIdx.x];
#pragma unroll
    for (int q = 0; q < 4; q++) {
        if (i + q < n) {
            int val = g_rowptr[i + q] + off;
            g_rowptr[i + q] = val;
            g_cursor[i + q] = val;
        }
    }
}

__global__ void k_scatter(const int* __restrict__ ei, int e, int n) {
    int idx = blockIdx.x * blockDim.x + threadIdx.x;
    if (idx < e) {
        int dst = ei[e + idx];
        int src = ei[idx];
        if ((unsigned)dst < (unsigned)n && (unsigned)src < (unsigned)n) {
            int pos = atomicAdd(&g_cursor[dst], 1);
            if ((unsigned)pos < (unsigned)EMAX) g_srcs[pos] = src;
        }
    }
}

// ---------- aggregation + split: warp per node, float4 lanes ----------------
__global__ __launch_bounds__(256) void k_aggregate(
    const float* __restrict__ xin, int use_x, int n)
{
    const int gw = (blockIdx.x * 256 + threadIdx.x) >> 5;   // global warp = node
    if (gw >= n) return;
    const int lane = threadIdx.x & 31;
    const float4* b4 = (const float4*)(use_x ? xin : g_h);

    float4 acc = b4[(size_t)gw * 32 + lane];
    int p = g_rowptr[gw];
    const int pe = g_rowptr[gw + 1];
    for (; p + 2 <= pe; p += 2) {
        int s0 = g_srcs[p], s1 = g_srcs[p + 1];
        float4 v0 = b4[(size_t)s0 * 32 + lane];
        float4 v1 = b4[(size_t)s1 * 32 + lane];
        acc.x += v0.x; acc.y += v0.y; acc.z += v0.z; acc.w += v0.w;
        acc.x += v1.x; acc.y += v1.y; acc.z += v1.z; acc.w += v1.w;
    }
    if (p < pe) {
        float4 v = b4[(size_t)g_srcs[p] * 32 + lane];
        acc.x += v.x; acc.y += v.y; acc.z += v.z; acc.w += v.w;
    }
    __nv_bfloat16 h0, l0, h1, l1, h2, l2, h3, l3;
    bsplit(acc.x, h0, l0); bsplit(acc.y, h1, l1);
    bsplit(acc.z, h2, l2); bsplit(acc.w, h3, l3);
    const size_t o = (size_t)gw * 64 + lane * 2;
    g_ah[o]     = packbf(h0, h1);
    g_ah[o + 1] = packbf(h2, h3);
    g_al[o]     = packbf(l0, l1);
    g_al[o + 1] = packbf(l2, l3);
}

// ---------------- fused MLP via mma.sync bf16x3 ------------------------------
#define BUFW     (128 * STRIDE)
#define WBUF     (128 * WSTR)
#define SMEM_MMA (1024 + 2 * BUFW * 4 + 2 * WBUF * 4)   // 107,520 B

__global__ __launch_bounds__(256) void k_mlp_mma(
    const float* __restrict__ b1g, const float* __restrict__ b2g,
    int lidx, unsigned dk0, unsigned dk1, int nrows)
{
    extern __shared__ char smem[];
    float*    sB1 = (float*)smem;
    float*    sB2 = (float*)(smem + 512);
    unsigned* sAh = (unsigned*)(smem + 1024);
    unsigned* sAl = sAh + BUFW;
    unsigned* sWh = sAl + BUFW;
    unsigned* sWl = sWh + WBUF;

    const int tid = threadIdx.x;
    const int wid = tid >> 5;
    const int lane = tid & 31;
    const int wr = wid & 3;
    const int wn = wid >> 2;
    const int g = lane >> 2;
    const int t = lane & 3;

    const int row0 = blockIdx.x * 128;
    const int avail = (nrows - row0 < 128) ? (nrows - row0) : 128;

    if (tid < 128) { sB1[tid] = b1g[tid]; sB2[tid] = b2g[tid]; }

    for (int i = tid; i < 2048; i += 256) {
        int r  = i >> 4;
        int w4 = (i & 15) * 4;
        uint4 vh = make_uint4(0, 0, 0, 0), vl = make_uint4(0, 0, 0, 0);
        if (r < avail) {
            vh = *(const uint4*)(g_ah + (size_t)(row0 + r) * 64 + w4);
            vl = *(const uint4*)(g_al + (size_t)(row0 + r) * 64 + w4);
        }
        *(uint4*)(sAh + r * STRIDE + w4) = vh;
        *(uint4*)(sAl + r * STRIDE + w4) = vl;
    }

    float acc[2][8][4];
#pragma unroll
    for (int mt = 0; mt < 2; mt++)
#pragma unroll
        for (int nt = 0; nt < 8; nt++)
#pragma unroll
            for (int q = 0; q < 4; q++) acc[mt][nt][q] = 0.f;

#pragma unroll 1
    for (int c = 0; c < 2; c++) {
        const unsigned* gh = g_wsph + ((lidx * 2 + 0) * 2 + c) * 4096;
        const unsigned* gl = g_wspl + ((lidx * 2 + 0) * 2 + c) * 4096;
        for (int i = tid; i < 1024; i += 256) {
            int nn = i >> 3;
            int w4 = (i & 7) * 4;
            *(uint4*)(sWh + nn * WSTR + w4) = *(const uint4*)(gh + nn * 32 + w4);
            *(uint4*)(sWl + nn * WSTR + w4) = *(const uint4*)(gl + nn * 32 + w4);
        }
        __syncthreads();
        gemm_chunk(sAh, sAl, sWh, sWl, acc, wr, wn, g, t, c * 32);
        __syncthreads();
    }

#pragma unroll
    for (int mt = 0; mt < 2; mt++) {
        const int r0 = wr * 32 + mt * 16 + g;
#pragma unroll
        for (int nt = 0; nt < 8; nt++) {
            const int c0 = wn * 64 + nt * 8 + 2 * t;
            const float bv0 = sB1[c0], bv1 = sB1[c0 + 1];
            float v00 = fmaxf(acc[mt][nt][0] + bv0, 0.f);
            float v01 = fmaxf(acc[mt][nt][1] + bv1, 0.f);
            float v10 = fmaxf(acc[mt][nt][2] + bv0, 0.f);
            float v11 = fmaxf(acc[mt][nt][3] + bv1, 0.f);
            __nv_bfloat16 h00, l00, h01, l01, h10, l10, h11, l11;
            bsplit(v00, h00, l00); bsplit(v01, h01, l01);
            bsplit(v10, h10, l10); bsplit(v11, h11, l11);
            const int w0 = r0 * STRIDE + (c0 >> 1);
            const int w1 = w0 + 8 * STRIDE;
            sAh[w0] = packbf(h00, h01);  sAl[w0] = packbf(l00, l01);
            sAh[w1] = packbf(h10, h11);  sAl[w1] = packbf(l10, l11);
            acc[mt][nt][0] = 0.f; acc[mt][nt][1] = 0.f;
            acc[mt][nt][2] = 0.f; acc[mt][nt][3] = 0.f;
        }
    }
    __syncthreads();

#pragma unroll 1
    for (int c = 0; c < 2; c++) {
        const unsigned* gh = g_wsph + ((lidx * 2 + 1) * 2 + c) * 4096;
        const unsigned* gl = g_wspl + ((lidx * 2 + 1) * 2 + c) * 4096;
        for (int i = tid; i < 1024; i += 256) {
            int nn = i >> 3;
            int w4 = (i & 7) * 4;
            *(uint4*)(sWh + nn * WSTR + w4) = *(const uint4*)(gh + nn * 32 + w4);
            *(uint4*)(sWl + nn * WSTR + w4) = *(const uint4*)(gl + nn * 32 + w4);
        }
        __syncthreads();
        gemm_chunk(sAh, sAl, sWh, sWl, acc, wr, wn, g, t, c * 32);
        __syncthreads();
    }

#pragma unroll
    for (int mt = 0; mt < 2; mt++) {
        const int r0 = wr * 32 + mt * 16 + g;
        const int grow0 = row0 + r0;
        const int grow1 = grow0 + 8;
#pragma unroll
        for (int nt = 0; nt < 8; nt++) {
            const int c0 = wn * 64 + nt * 8 + 2 * t;
            const float bv0 = sB2[c0], bv1 = sB2[c0 + 1];
            if (grow0 < nrows) {
                unsigned j = (unsigned)grow0 * (unsigned)DIM + (unsigned)c0;
                float v0 = fmaxf(acc[mt][nt][0] + bv0, 0.f) * dropout_mult(dk0, dk1, j);
                float v1 = fmaxf(acc[mt][nt][1] + bv1, 0.f) * dropout_mult(dk0, dk1, j + 1);
                *(float2*)(g_h + (size_t)grow0 * DIM + c0) = make_float2(v0, v1);
            }
            if (grow1 < nrows) {
                unsigned j = (unsigned)grow1 * (unsigned)DIM + (unsigned)c0;
                float v0 = fmaxf(acc[mt][nt][2] + bv0, 0.f) * dropout_mult(dk0, dk1, j);
                float v1 = fmaxf(acc[mt][nt][3] + bv1, 0.f) * dropout_mult(dk0, dk1, j + 1);
                *(float2*)(g_h + (size_t)grow1 * DIM + c0) = make_float2(v0, v1);
            }
        }
    }
}

// ---------------- final linear: out = g_h @ Wlin + blin (128 -> 64) --------
__global__ __launch_bounds__(256, 1) void k_linear(
    const float* __restrict__ Wg, const float* __restrict__ bg,
    float* __restrict__ out, int nrows)
{
    __shared__ float sA[128 * PAD];
    __shared__ float sW[32 * 64];

    const int tid = threadIdx.x;
    const int tx4 = (tid & 15) * 4;
    const int ty8 = (tid >> 4) * 8;
    const int row0 = blockIdx.x * 128;
    const int avail = (nrows - row0 < 128) ? (nrows - row0) : 128;

    float acc[8][4];
#pragma unroll
    for (int r = 0; r < 8; r++)
#pragma unroll
        for (int c = 0; c < 4; c++) acc[r][c] = 0.0f;

    for (int kc = 0; kc < 128; kc += 32) {
#pragma unroll
        for (int i = tid; i < 1024; i += 256) {
            int r = i >> 3;
            int c4 = (i & 7) * 4;
            float4 v = make_float4(0.f, 0.f, 0.f, 0.f);
            if (r < avail)
                v = *(const float4*)(g_h + (size_t)(row0 + r) * DIM + kc + c4);
            *(float4*)(sA + r * PAD + c4) = v;
        }
#pragma unroll
        for (int i = tid; i < 512; i += 256) {
            int r = i >> 4;
            int c4 = (i & 15) * 4;
            *(float4*)(sW + r * 64 + c4) =
                *(const float4*)(Wg + (size_t)(kc + r) * ODIM + c4);
        }
        __syncthreads();

#pragma unroll
        for (int k = 0; k < 32; k += 4) {
            float4 a[8];
#pragma unroll
            for (int r = 0; r < 8; r++)
                a[r] = *(const float4*)(sA + (ty8 + r) * PAD + k);
#pragma unroll
            for (int kk = 0; kk < 4; kk++) {
                const float4 w = *(const float4*)(sW + (k + kk) * 64 + tx4);
#pragma unroll
                for (int r = 0; r < 8; r++) {
                    const float av = (kk == 0) ? a[r].x : (kk == 1) ? a[r].y
                                   : (kk == 2) ? a[r].z : a[r].w;
                    acc[r][0] = fmaf(av, w.x, acc[r][0]);
                    acc[r][1] = fmaf(av, w.y, acc[r][1]);
                    acc[r][2] = fmaf(av, w.z, acc[r][2]);
                    acc[r][3] = fmaf(av, w.w, acc[r][3]);
                }
            }
        }
        __syncthreads();
    }

    float b[4];
#pragma unroll
    for (int c = 0; c < 4; c++) b[c] = bg[tx4 + c];
#pragma unroll
    for (int r = 0; r < 8; r++) {
        int grow = row0 + ty8 + r;
        if (grow >= nrows) break;
        *(float4*)(out + (size_t)grow * ODIM + tx4) =
            make_float4(acc[r][0] + b[0], acc[r][1] + b[1],
                        acc[r][2] + b[2], acc[r][3] + b[3]);
    }
}

// ---------------- launch ----------------------------------------------------
extern "C" void kernel_launch(void* const* d_in, const int* in_sizes, int n_in,
                              void* d_out, int out_size)
{
    const float* x    = (const float*)d_in[0];
    const int*   ei   = (const int*)d_in[1];
    const float* Ws1  = (const float*)d_in[2];
    const float* bs1  = (const float*)d_in[3];
    const float* Ws2  = (const float*)d_in[4];
    const float* bs2  = (const float*)d_in[5];
    const float* Wlin = (const float*)d_in[6];
    const float* blin = (const float*)d_in[7];
    float*       out  = (float*)d_out;

    const int n = in_sizes[0] / DIM;
    const int e = in_sizes[1] / 2;
    if (n > NMAX || e > EMAX || n <= 0) return;

    cudaFuncSetAttribute(k_mlp_mma, cudaFuncAttributeMaxDynamicSharedMemorySize, SMEM_MMA);

    unsigned dk0[3], dk1[3];
    for (int l = 0; l < 3; l++)
        threefry2x32(0u, 42u, 0u, (unsigned)l, dk0[l], dk1[l]);

    const int nsb = (n + SCANB - 1) / SCANB;   // scan blocks (13 for n=50k)

    k_split_w<<<(3 * 2 * 2 * 4096 + 255) / 256, 256>>>(Ws1, Ws2);
    k_zero   <<<(n + 255) / 256, 256>>>(n);
    k_hist   <<<(e + 255) / 256, 256>>>(ei, e, n);
    k_scan1  <<<nsb, 1024>>>(n);
    k_scan2  <<<1, 32>>>(nsb, n);
    k_scan3  <<<nsb, 1024>>>(n);
    k_scatter<<<(e + 255) / 256, 256>>>(ei, e, n);

    const int gblk = (n + 127) / 128;
    const int ablk = (n * 32 + 255) / 256;     // warp per node
    for (int l = 0; l < 3; l++) {
        k_aggregate<<<ablk, 256>>>(x, l == 0 ? 1 : 0, n);
        k_mlp_mma<<<gblk, 256, SMEM_MMA>>>(
            bs1 + (size_t)l * DIM, bs2 + (size_t)l * DIM,
            l, dk0[l], dk1[l], n);
    }
    k_linear<<<gblk, 256>>>(Wlin, blin, out, n);
}